// round 8
// baseline (speedup 1.0000x reference)
#include <cuda_runtime.h>
#include <cstdint>

// ---------------------------------------------------------------------------
// CRSD block: 2-layer leaky reservoir RNN.
//   B=32, T=1024, D=R=1024, ALPHA=0.1
// Strategy: persistent-cooperative scan kernel, weights in SMEM, fp32 with
// packed fma.rn.f32x2, custom grid barrier (2 per timestep).
// ---------------------------------------------------------------------------

#define B_DIM 32
#define T_DIM 1024
#define D_DIM 1024
#define TD_STRIDE (T_DIM * D_DIM)   // 1048576
#define GRID_CTAS 128
#define NTHR 256

typedef unsigned long long ull;

// Scratch: activations in transposed layout [t][k][b] (b contiguous). 128MB.
__device__ float g_buf[(size_t)T_DIM * D_DIM * B_DIM];
__device__ float g_hT[D_DIM * B_DIM];   // hidden state, [k][b]
__device__ float g_rT[D_DIM * B_DIM];   // reservoir state, [k][b]
__device__ unsigned g_bar_count = 0;
__device__ unsigned g_bar_epoch = 0;

// ---- packed fp32x2 helpers (FFMA2: 2 FMA lanes per issue slot) ------------
__device__ __forceinline__ ull pk2(float w) {
    ull r;
    asm("mov.b64 %0, {%1, %1};" : "=l"(r) : "f"(w));
    return r;
}
__device__ __forceinline__ void ffma2(ull& acc, ull a, ull w) {
    asm("fma.rn.f32x2 %0, %1, %2, %0;" : "+l"(acc) : "l"(a), "l"(w));
}
// L2-coherent 16B load (bypass non-coherent L1 for cross-SM state).
__device__ __forceinline__ ulonglong2 ldcg2(const float* p) {
    ulonglong2 v;
    asm volatile("ld.global.cg.v2.u64 {%0, %1}, [%2];"
                 : "=l"(v.x), "=l"(v.y) : "l"(p));
    return v;
}

// ---- grid-wide barrier (all 128 CTAs co-resident: 1 CTA/SM via smem) ------
__device__ __forceinline__ void grid_barrier(unsigned& epoch) {
    __syncthreads();
    if (threadIdx.x == 0) {
        unsigned next = epoch + 1u;
        __threadfence();                       // publish my CTA's writes
        unsigned old = atomicAdd(&g_bar_count, 1u);
        if (old == GRID_CTAS - 1u) {
            atomicExch(&g_bar_count, 0u);      // reset BEFORE release
            __threadfence();
            atomicExch(&g_bar_epoch, next);    // release
        } else {
            while (*((volatile unsigned*)&g_bar_epoch) != next) { }
        }
        epoch = next;
    }
    __syncthreads();
}

// ---------------------------------------------------------------------------
// Persistent scan kernel: one launch runs a full layer (1024 timesteps).
// CTA c owns output columns [c*8, c*8+8) of BOTH the r-space and h-space.
// SMEM: WA[2048][16] (k<1024: Wxr|Wxh rows, k>=1024: Whr|Whh rows; cols 0-7
// feed r, cols 8-15 feed h), WB[1024][8] (Wrh), plus reduction buffers.
// ---------------------------------------------------------------------------
#define SMEM_FLOATS (2048*16 + 1024*8 + 4096 + 256 + 256)
#define SMEM_BYTES  (SMEM_FLOATS * 4)

__global__ void __launch_bounds__(NTHR, 1)
scan_kernel(const float* __restrict__ Wxh, const float* __restrict__ Whh,
            const float* __restrict__ Wrh, const float* __restrict__ Wxr,
            const float* __restrict__ Whr, int layer)
{
    extern __shared__ float sm[];
    float* WA  = sm;                    // 2048*16
    float* WB  = WA + 2048 * 16;        // 1024*8
    float* RED = WB + 1024 * 8;         // 8*16*32 (reused in phase B as 8*8*32)
    float* Ps  = RED + 4096;            // 8*32  pre-activation stash
    float* Rs  = Ps + 256;              // 8*32  local copy of owned r columns

    const int tid  = threadIdx.x;
    const int cta  = blockIdx.x;
    const int c8   = cta * 8;
    const int lane = tid & 31;
    const int warp = tid >> 5;

    const size_t DR = (size_t)D_DIM * D_DIM;
    const float* wxh = Wxh + (size_t)layer * DR;
    const float* whh = Whh + (size_t)layer * DR;
    const float* wrh = Wrh + (size_t)layer * DR;
    const float* wxr = Wxr + (size_t)layer * DR;
    const float* whr = Whr + (size_t)layer * DR;

    // ---- load this CTA's weight slices into SMEM (once per layer) ----
    for (int i = tid; i < 8192; i += NTHR) {          // k in [0,1024), jc in [0,8)
        int k  = i >> 3;
        int jc = i & 7;
        int g  = k * D_DIM + c8 + jc;
        WA[k * 16 + jc]              = wxr[g];
        WA[k * 16 + 8 + jc]          = wxh[g];
        WA[(k + 1024) * 16 + jc]     = whr[g];
        WA[(k + 1024) * 16 + 8 + jc] = whh[g];
        WB[k * 8 + jc]               = wrh[g];
    }
    // ---- zero state (h=0, r=0 at layer start, per reference) ----
    {
        Rs[tid] = 0.0f;
        int j = tid >> 5, b = tid & 31;
        g_hT[(c8 + j) * 32 + b] = 0.0f;
    }
    unsigned epoch = *((volatile unsigned*)&g_bar_epoch);
    __threadfence();
    grid_barrier(epoch);   // all weights loaded, all state zeroed & visible

    const int jj = lane >> 2;   // 0..7 : column pair (jj, jj+8) in phase A
    const int bb = lane & 3;    // 0..3 : batch group of 8 (b = bb*8 .. bb*8+7)

    for (int t = 0; t < T_DIM; ++t) {
        // ================= PHASE A =================
        // U[32,16] = [x_t ; h] (32x2048) @ WA (2048x16); warp w owns k-slice
        // [w*256, w*256+256). Warps 0-3 read x_t (g_buf), 4-7 read hT.
        {
            ull acc[8];
            #pragma unroll
            for (int i = 0; i < 8; ++i) acc[i] = 0ULL;

            const float* Abase = (warp < 4)
                ? (g_buf + (size_t)t * (D_DIM * B_DIM) + warp * 8192 + bb * 8)
                : (g_hT + (warp - 4) * 8192 + bb * 8);
            const float* Wb = WA + warp * 4096;   // warp*256 rows * 16

            #pragma unroll 4
            for (int kl = 0; kl < 256; ++kl) {
                ulonglong2 a01 = ldcg2(Abase + kl * 32);
                ulonglong2 a23 = ldcg2(Abase + kl * 32 + 4);
                float w0 = Wb[kl * 16 + jj];
                float w1 = Wb[kl * 16 + 8 + jj];
                ull wp0 = pk2(w0);
                ull wp1 = pk2(w1);
                ffma2(acc[0], a01.x, wp0);
                ffma2(acc[1], a01.y, wp0);
                ffma2(acc[2], a23.x, wp0);
                ffma2(acc[3], a23.y, wp0);
                ffma2(acc[4], a01.x, wp1);
                ffma2(acc[5], a01.y, wp1);
                ffma2(acc[6], a23.x, wp1);
                ffma2(acc[7], a23.y, wp1);
            }
            // stash partials: RED[warp][j][b]
            float* rw = RED + warp * 512;
            ull* p0 = (ull*)(rw + jj * 32 + bb * 8);
            p0[0] = acc[0]; p0[1] = acc[1]; p0[2] = acc[2]; p0[3] = acc[3];
            ull* p1 = (ull*)(rw + (jj + 8) * 32 + bb * 8);
            p1[0] = acc[4]; p1[1] = acc[5]; p1[2] = acc[6]; p1[3] = acc[7];
        }
        __syncthreads();
        // cross-warp reduce + r update / p stash
        #pragma unroll
        for (int o = tid; o < 512; o += NTHR) {
            float s = 0.0f;
            #pragma unroll
            for (int w = 0; w < 8; ++w) s += RED[w * 512 + o];
            int j = o >> 5, b = o & 31;
            if (j < 8) {
                float g  = tanhf(s);
                float rn = 0.9f * Rs[o] + 0.1f * g;
                Rs[o] = rn;
                g_rT[(c8 + j) * 32 + b] = rn;      // publish r_new
            } else {
                Ps[o - 256] = s;                    // x@Wxh + h@Whh
            }
        }
        __threadfence();
        grid_barrier(epoch);   // r_new globally visible

        // ================= PHASE B =================
        // Z[32,8] = r_new (32x1024) @ WB (1024x8); warp w owns 128 k's.
        {
            ull acc[4];
            #pragma unroll
            for (int i = 0; i < 4; ++i) acc[i] = 0ULL;

            const float* Rb = g_rT + warp * 4096 + bb * 8;   // warp*128 rows *32
            const float* Wb = WB + warp * 1024;              // warp*128 rows * 8

            #pragma unroll 4
            for (int kl = 0; kl < 128; ++kl) {
                ulonglong2 a01 = ldcg2(Rb + kl * 32);
                ulonglong2 a23 = ldcg2(Rb + kl * 32 + 4);
                float w = Wb[kl * 8 + jj];
                ull wp = pk2(w);
                ffma2(acc[0], a01.x, wp);
                ffma2(acc[1], a01.y, wp);
                ffma2(acc[2], a23.x, wp);
                ffma2(acc[3], a23.y, wp);
            }
            float* rw = RED + warp * 256;
            ull* p0 = (ull*)(rw + jj * 32 + bb * 8);
            p0[0] = acc[0]; p0[1] = acc[1]; p0[2] = acc[2]; p0[3] = acc[3];
        }
        __syncthreads();
        {
            float z = 0.0f;
            #pragma unroll
            for (int w = 0; w < 8; ++w) z += RED[w * 256 + tid];
            int j = tid >> 5, b = tid & 31;
            float hn = tanhf(Ps[tid] + z);
            g_hT[(c8 + j) * 32 + b] = hn;                               // state
            g_buf[(size_t)t * (D_DIM * B_DIM) + (c8 + j) * 32 + b] = hn; // output (in-place over x_t)
        }
        __threadfence();
        grid_barrier(epoch);   // h_new visible before next step's phase A
    }
}

// ---------------------------------------------------------------------------
// Transposes: x[b][t][k]  <->  buf[t][k][b]
// ---------------------------------------------------------------------------
__global__ void transpose_in(const float* __restrict__ x)
{
    __shared__ float s[32][65];
    const int t  = blockIdx.y;
    const int k0 = blockIdx.x * 64;
    const int tid = threadIdx.x;

    #pragma unroll
    for (int p = 0; p < 8; ++p) {
        int b  = p * 4 + (tid >> 6);
        int kk = tid & 63;
        s[b][kk] = x[(size_t)b * TD_STRIDE + (size_t)t * D_DIM + k0 + kk];
    }
    __syncthreads();
    #pragma unroll
    for (int p = 0; p < 8; ++p) {
        int kk = p * 8 + (tid >> 5);
        int b  = tid & 31;
        g_buf[(size_t)t * (D_DIM * B_DIM) + (size_t)(k0 + kk) * 32 + b] = s[b][kk];
    }
}

__global__ void transpose_out(float* __restrict__ out)
{
    __shared__ float s[64][33];
    const int t  = blockIdx.y;
    const int j0 = blockIdx.x * 64;
    const int tid = threadIdx.x;

    #pragma unroll
    for (int p = 0; p < 8; ++p) {
        int jj = p * 8 + (tid >> 5);
        int b  = tid & 31;
        s[jj][b] = g_buf[(size_t)t * (D_DIM * B_DIM) + (size_t)(j0 + jj) * 32 + b];
    }
    __syncthreads();
    #pragma unroll
    for (int p = 0; p < 8; ++p) {
        int b  = p * 4 + (tid >> 6);
        int jc = tid & 63;
        out[(size_t)b * TD_STRIDE + (size_t)t * D_DIM + j0 + jc] = s[jc][b];
    }
}

// ---------------------------------------------------------------------------
extern "C" void kernel_launch(void* const* d_in, const int* in_sizes, int n_in,
                              void* d_out, int out_size)
{
    const float* x   = (const float*)d_in[0];
    const float* Wxh = (const float*)d_in[1];
    const float* Whh = (const float*)d_in[2];
    const float* Wrh = (const float*)d_in[3];
    const float* Wxr = (const float*)d_in[4];
    const float* Whr = (const float*)d_in[5];
    float* out = (float*)d_out;

    cudaFuncSetAttribute(scan_kernel,
                         cudaFuncAttributeMaxDynamicSharedMemorySize,
                         SMEM_BYTES);

    transpose_in<<<dim3(16, 1024), NTHR>>>(x);
    scan_kernel<<<GRID_CTAS, NTHR, SMEM_BYTES>>>(Wxh, Whh, Wrh, Wxr, Whr, 0);
    scan_kernel<<<GRID_CTAS, NTHR, SMEM_BYTES>>>(Wxh, Whh, Wrh, Wxr, Whr, 1);
    transpose_out<<<dim3(16, 1024), NTHR>>>(out);
}

// round 9
// speedup vs baseline: 1.8237x; 1.8237x over previous
#include <cuda_runtime.h>
#include <cstdint>

// ---------------------------------------------------------------------------
// CRSD block: 2-layer leaky reservoir RNN.  B=32, T=1024, D=R=1024, ALPHA=0.1
// v2: persistent scan, weights in SMEM, activations staged via cp.async.cg
// (L2-coherent, high-MLP) into double-buffered SMEM chunks; compute is
// LDS + packed fma.rn.f32x2 and is FMA-pipe bound.
// ---------------------------------------------------------------------------

#define B_DIM 32
#define T_DIM 1024
#define D_DIM 1024
#define TD_STRIDE (T_DIM * T_DIM)          // 1024*1024 (t-major per batch)
#define GRID_CTAS 128
#define NTHR 256
#define CHUNK_ROWS 128
#define CHUNK_FLOATS (CHUNK_ROWS * 32)     // 4096 floats = 16KB

typedef unsigned long long ull;

// Activations, transposed layout [t][k][b] (b contiguous). 128MB scratch.
__device__ float g_buf[(size_t)T_DIM * D_DIM * B_DIM];
__device__ float g_hT[D_DIM * B_DIM];      // hidden state  [k][b]
__device__ float g_rT[D_DIM * B_DIM];      // reservoir     [k][b]
__device__ unsigned g_bar_count = 0;
__device__ unsigned g_bar_epoch = 0;

// ---- packed fp32x2 helpers -------------------------------------------------
__device__ __forceinline__ ull pk2(float w) {
    ull r;
    asm("mov.b64 %0, {%1, %1};" : "=l"(r) : "f"(w));
    return r;
}
__device__ __forceinline__ void ffma2(ull& acc, ull a, ull w) {
    asm("fma.rn.f32x2 %0, %1, %2, %0;" : "+l"(acc) : "l"(a), "l"(w));
}

// ---- cp.async.cg (LDGSTS, L2-sourced => coherent across SMs) ---------------
__device__ __forceinline__ unsigned smem_u32(const void* p) {
    unsigned a;
    asm("{ .reg .u64 t; cvta.to.shared.u64 t, %1; cvt.u32.u64 %0, t; }"
        : "=r"(a) : "l"(p));
    return a;
}
#define CP_COMMIT() asm volatile("cp.async.commit_group;" ::: "memory")
#define CP_WAIT0()  asm volatile("cp.async.wait_group 0;" ::: "memory")
#define CP_WAIT1()  asm volatile("cp.async.wait_group 1;" ::: "memory")

// copy one 16KB chunk (4096 floats) global->smem; all 256 threads, 4x16B each
__device__ __forceinline__ void cp_chunk(float* dst, const float* src, int tid) {
    unsigned sb = smem_u32(dst) + tid * 16;
    const float* gp = src + tid * 4;
    #pragma unroll
    for (int i = 0; i < 4; ++i) {
        asm volatile("cp.async.cg.shared.global [%0], [%1], 16;"
                     :: "r"(sb + i * 4096), "l"(gp + i * 1024) : "memory");
    }
    CP_COMMIT();
}

// ---- grid-wide barrier (128 CTAs co-resident, 1/SM) ------------------------
__device__ __forceinline__ void grid_barrier(unsigned& epoch) {
    __syncthreads();
    if (threadIdx.x == 0) {
        unsigned next = epoch + 1u;
        __threadfence();
        unsigned old = atomicAdd(&g_bar_count, 1u);
        if (old == GRID_CTAS - 1u) {
            atomicExch(&g_bar_count, 0u);
            __threadfence();
            atomicExch(&g_bar_epoch, next);
        } else {
            while (*((volatile unsigned*)&g_bar_epoch) != next) { }
        }
        epoch = next;
    }
    __syncthreads();
}

// ---------------------------------------------------------------------------
// SMEM: WA[2048][16] (rows 0-1023: Wxr|Wxh, rows 1024-2047: Whr|Whh; cols 0-7
// feed r-space, 8-15 feed h-space), WB[1024][8] (Wrh), RED (8*16*32),
// Ps/Rs (8*32 each), ACT (2 x 16KB chunk buffers).
// Total = 32768+8192+4096+256+256+8192 floats = 215,040 B.
// ---------------------------------------------------------------------------
#define SMEM_FLOATS (2048*16 + 1024*8 + 4096 + 256 + 256 + 2*CHUNK_FLOATS)
#define SMEM_BYTES  (SMEM_FLOATS * 4)

__global__ void __launch_bounds__(NTHR, 1)
scan_kernel(const float* __restrict__ Wxh, const float* __restrict__ Whh,
            const float* __restrict__ Wrh, const float* __restrict__ Wxr,
            const float* __restrict__ Whr, int layer)
{
    extern __shared__ float sm[];
    float* WA  = sm;                        // 2048*16
    float* WB  = WA + 2048 * 16;            // 1024*8
    float* RED = WB + 1024 * 8;             // 4096
    float* Ps  = RED + 4096;                // 256
    float* Rs  = Ps + 256;                  // 256
    float* ACT = Rs + 256;                  // 2 * 4096

    const int tid  = threadIdx.x;
    const int cta  = blockIdx.x;
    const int c8   = cta * 8;
    const int lane = tid & 31;
    const int warp = tid >> 5;

    const size_t DR = (size_t)D_DIM * D_DIM;
    const float* wxh = Wxh + (size_t)layer * DR;
    const float* whh = Whh + (size_t)layer * DR;
    const float* wrh = Wrh + (size_t)layer * DR;
    const float* wxr = Wxr + (size_t)layer * DR;
    const float* whr = Whr + (size_t)layer * DR;

    // ---- weight slices -> SMEM (once per layer) ----
    for (int i = tid; i < 8192; i += NTHR) {
        int k  = i >> 3;
        int jc = i & 7;
        int g  = k * D_DIM + c8 + jc;
        WA[k * 16 + jc]              = wxr[g];
        WA[k * 16 + 8 + jc]          = wxh[g];
        WA[(k + 1024) * 16 + jc]     = whr[g];
        WA[(k + 1024) * 16 + 8 + jc] = whh[g];
        WB[k * 8 + jc]               = wrh[g];
    }
    // ---- zero state ----
    {
        Rs[tid] = 0.0f;
        int j = tid >> 5, b = tid & 31;
        g_hT[(c8 + j) * 32 + b] = 0.0f;
    }
    unsigned epoch = *((volatile unsigned*)&g_bar_epoch);
    __threadfence();
    grid_barrier(epoch);

    const int jj = lane >> 2;   // 0..7 : column (pair) index
    const int bb = lane & 3;    // 0..3 : batch octet

    for (int t = 0; t < T_DIM; ++t) {
        const float* xsrc = g_buf + (size_t)t * (D_DIM * B_DIM);

        // ================= PHASE A =================
        // U[32,16] = [x_t ; h] (32x2048) @ WA(2048x16).
        // 16 chunks of 128 rows: 0-7 from x_t, 8-15 from g_hT.
        {
            cp_chunk(ACT,                xsrc,                tid);
            cp_chunk(ACT + CHUNK_FLOATS, xsrc + CHUNK_FLOATS, tid);

            ull acc[8];
            #pragma unroll
            for (int i = 0; i < 8; ++i) acc[i] = 0ULL;

            #pragma unroll 1
            for (int c = 0; c < 16; ++c) {
                if (c + 1 < 16) { CP_WAIT1(); } else { CP_WAIT0(); }
                __syncthreads();

                const float* cb   = ACT + (c & 1) * CHUNK_FLOATS;
                const float* arow = cb + warp * (16 * 32) + bb * 8;
                const float* wrow = WA + (c * 128 + warp * 16) * 16;

                #pragma unroll
                for (int kl = 0; kl < 16; ++kl) {
                    ulonglong2 a01 = *(const ulonglong2*)(arow + kl * 32);
                    ulonglong2 a23 = *(const ulonglong2*)(arow + kl * 32 + 4);
                    ull wp0 = pk2(wrow[kl * 16 + jj]);
                    ull wp1 = pk2(wrow[kl * 16 + 8 + jj]);
                    ffma2(acc[0], a01.x, wp0);
                    ffma2(acc[1], a01.y, wp0);
                    ffma2(acc[2], a23.x, wp0);
                    ffma2(acc[3], a23.y, wp0);
                    ffma2(acc[4], a01.x, wp1);
                    ffma2(acc[5], a01.y, wp1);
                    ffma2(acc[6], a23.x, wp1);
                    ffma2(acc[7], a23.y, wp1);
                }
                __syncthreads();
                if (c + 2 < 16) {
                    int nc = c + 2;
                    const float* src = (nc < 8)
                        ? (xsrc + nc * CHUNK_FLOATS)
                        : (g_hT + (nc - 8) * CHUNK_FLOATS);
                    cp_chunk(ACT + (c & 1) * CHUNK_FLOATS, src, tid);
                }
            }

            // stash partials: RED[warp][j][b]
            float* rw = RED + warp * 512;
            ull* p0 = (ull*)(rw + jj * 32 + bb * 8);
            p0[0] = acc[0]; p0[1] = acc[1]; p0[2] = acc[2]; p0[3] = acc[3];
            ull* p1 = (ull*)(rw + (jj + 8) * 32 + bb * 8);
            p1[0] = acc[4]; p1[1] = acc[5]; p1[2] = acc[6]; p1[3] = acc[7];
        }
        __syncthreads();
        // cross-warp reduce + r update / p stash
        #pragma unroll
        for (int o = tid; o < 512; o += NTHR) {
            float s = 0.0f;
            #pragma unroll
            for (int w = 0; w < 8; ++w) s += RED[w * 512 + o];
            int j = o >> 5, b = o & 31;
            if (j < 8) {
                float g  = tanhf(s);
                float rn = 0.9f * Rs[o] + 0.1f * g;
                Rs[o] = rn;
                g_rT[(c8 + j) * 32 + b] = rn;
            } else {
                Ps[o - 256] = s;
            }
        }
        __threadfence();
        grid_barrier(epoch);   // r_new globally visible

        // ================= PHASE B =================
        // Z[32,8] = r_new (32x1024) @ WB(1024x8). 8 chunks of 128 rows.
        {
            cp_chunk(ACT,                g_rT,                tid);
            cp_chunk(ACT + CHUNK_FLOATS, g_rT + CHUNK_FLOATS, tid);

            ull acc[4];
            #pragma unroll
            for (int i = 0; i < 4; ++i) acc[i] = 0ULL;

            #pragma unroll 1
            for (int c = 0; c < 8; ++c) {
                if (c + 1 < 8) { CP_WAIT1(); } else { CP_WAIT0(); }
                __syncthreads();

                const float* cb   = ACT + (c & 1) * CHUNK_FLOATS;
                const float* arow = cb + warp * (16 * 32) + bb * 8;
                const float* wrow = WB + (c * 128 + warp * 16) * 8;

                #pragma unroll
                for (int kl = 0; kl < 16; ++kl) {
                    ulonglong2 a01 = *(const ulonglong2*)(arow + kl * 32);
                    ulonglong2 a23 = *(const ulonglong2*)(arow + kl * 32 + 4);
                    ull wp = pk2(wrow[kl * 8 + jj]);
                    ffma2(acc[0], a01.x, wp);
                    ffma2(acc[1], a01.y, wp);
                    ffma2(acc[2], a23.x, wp);
                    ffma2(acc[3], a23.y, wp);
                }
                __syncthreads();
                if (c + 2 < 8) {
                    cp_chunk(ACT + (c & 1) * CHUNK_FLOATS,
                             g_rT + (c + 2) * CHUNK_FLOATS, tid);
                }
            }

            float* rw = RED + warp * 256;
            ull* p0 = (ull*)(rw + jj * 32 + bb * 8);
            p0[0] = acc[0]; p0[1] = acc[1]; p0[2] = acc[2]; p0[3] = acc[3];
        }
        __syncthreads();
        {
            float z = 0.0f;
            #pragma unroll
            for (int w = 0; w < 8; ++w) z += RED[w * 256 + tid];
            int j = tid >> 5, b = tid & 31;
            float hn = tanhf(Ps[tid] + z);
            g_hT[(c8 + j) * 32 + b] = hn;
            g_buf[(size_t)t * (D_DIM * B_DIM) + (c8 + j) * 32 + b] = hn;
        }
        __threadfence();
        grid_barrier(epoch);   // h_new visible before next step
    }
}

// ---------------------------------------------------------------------------
// Transposes: x[b][t][k]  <->  buf[t][k][b]
// ---------------------------------------------------------------------------
__global__ void transpose_in(const float* __restrict__ x)
{
    __shared__ float s[32][65];
    const int t  = blockIdx.y;
    const int k0 = blockIdx.x * 64;
    const int tid = threadIdx.x;

    #pragma unroll
    for (int p = 0; p < 8; ++p) {
        int b  = p * 4 + (tid >> 6);
        int kk = tid & 63;
        s[b][kk] = x[(size_t)b * TD_STRIDE + (size_t)t * D_DIM + k0 + kk];
    }
    __syncthreads();
    #pragma unroll
    for (int p = 0; p < 8; ++p) {
        int kk = p * 8 + (tid >> 5);
        int b  = tid & 31;
        g_buf[(size_t)t * (D_DIM * B_DIM) + (size_t)(k0 + kk) * 32 + b] = s[b][kk];
    }
}

__global__ void transpose_out(float* __restrict__ out)
{
    __shared__ float s[64][33];
    const int t  = blockIdx.y;
    const int j0 = blockIdx.x * 64;
    const int tid = threadIdx.x;

    #pragma unroll
    for (int p = 0; p < 8; ++p) {
        int jj = p * 8 + (tid >> 5);
        int b  = tid & 31;
        s[jj][b] = g_buf[(size_t)t * (D_DIM * B_DIM) + (size_t)(j0 + jj) * 32 + b];
    }
    __syncthreads();
    #pragma unroll
    for (int p = 0; p < 8; ++p) {
        int b  = p * 4 + (tid >> 6);
        int jc = tid & 63;
        out[(size_t)b * TD_STRIDE + (size_t)t * D_DIM + j0 + jc] = s[jc][b];
    }
}

// ---------------------------------------------------------------------------
extern "C" void kernel_launch(void* const* d_in, const int* in_sizes, int n_in,
                              void* d_out, int out_size)
{
    const float* x   = (const float*)d_in[0];
    const float* Wxh = (const float*)d_in[1];
    const float* Whh = (const float*)d_in[2];
    const float* Wrh = (const float*)d_in[3];
    const float* Wxr = (const float*)d_in[4];
    const float* Whr = (const float*)d_in[5];
    float* out = (float*)d_out;

    cudaFuncSetAttribute(scan_kernel,
                         cudaFuncAttributeMaxDynamicSharedMemorySize,
                         SMEM_BYTES);

    transpose_in<<<dim3(16, 1024), NTHR>>>(x);
    scan_kernel<<<GRID_CTAS, NTHR, SMEM_BYTES>>>(Wxh, Whh, Wrh, Wxr, Whr, 0);
    scan_kernel<<<GRID_CTAS, NTHR, SMEM_BYTES>>>(Wxh, Whh, Wrh, Wxr, Whr, 1);
    transpose_out<<<dim3(16, 1024), NTHR>>>(out);
}

// round 10
// speedup vs baseline: 1.8270x; 1.0018x over previous
#include <cuda_runtime.h>
#include <cstdint>

// ---------------------------------------------------------------------------
// CRSD block: 2-layer leaky reservoir RNN.  B=32, T=1024, D=R=1024, ALPHA=0.1
// v3: persistent scan, weights in SMEM, activations streamed via cp.async.cg
// with a DEPTH-3 x 16KB ring (48KB outstanding = bandwidth-delay product),
// uniform wait_group-2 discipline, and cross-step x-prefetch.
// ---------------------------------------------------------------------------

#define B_DIM 32
#define T_DIM 1024
#define D_DIM 1024
#define TD_STRIDE (T_DIM * T_DIM)
#define GRID_CTAS 128
#define NTHR 256
#define CHUNK_FLOATS 4096              // 128 rows x 32 batch = 16KB
#define NBUF 3

typedef unsigned long long ull;

__device__ float g_buf[(size_t)T_DIM * D_DIM * B_DIM];  // [t][k][b]
__device__ float g_hT[D_DIM * B_DIM];                    // [k][b]
__device__ float g_rT[D_DIM * B_DIM];                    // [k][b]
__device__ unsigned g_bar_count = 0;
__device__ unsigned g_bar_epoch = 0;

// ---- packed fp32x2 helpers -------------------------------------------------
__device__ __forceinline__ ull pk2(float w) {
    ull r;
    asm("mov.b64 %0, {%1, %1};" : "=l"(r) : "f"(w));
    return r;
}
__device__ __forceinline__ void ffma2(ull& acc, ull a, ull w) {
    asm("fma.rn.f32x2 %0, %1, %2, %0;" : "+l"(acc) : "l"(a), "l"(w));
}

// ---- cp.async.cg (L2-sourced => coherent across SMs) ------------------------
__device__ __forceinline__ unsigned smem_u32(const void* p) {
    unsigned a;
    asm("{ .reg .u64 t; cvta.to.shared.u64 t, %1; cvt.u32.u64 %0, t; }"
        : "=r"(a) : "l"(p));
    return a;
}
#define CP_COMMIT_EMPTY() asm volatile("cp.async.commit_group;" ::: "memory")
#define CP_WAIT2()        asm volatile("cp.async.wait_group 2;" ::: "memory")

// copy one 16KB chunk global->smem; 256 threads x 4 x 16B; commits a group
__device__ __forceinline__ void cp_chunk(float* dst, const float* src, int tid) {
    unsigned sb = smem_u32(dst) + tid * 16;
    const float* gp = src + tid * 4;
    #pragma unroll
    for (int i = 0; i < 4; ++i) {
        asm volatile("cp.async.cg.shared.global [%0], [%1], 16;"
                     :: "r"(sb + i * 4096), "l"(gp + i * 1024) : "memory");
    }
    asm volatile("cp.async.commit_group;" ::: "memory");
}

// ---- grid-wide barrier (128 CTAs co-resident, 1/SM) -------------------------
__device__ __forceinline__ void grid_barrier(unsigned& epoch) {
    __syncthreads();
    if (threadIdx.x == 0) {
        unsigned next = epoch + 1u;
        __threadfence();
        unsigned old = atomicAdd(&g_bar_count, 1u);
        if (old == GRID_CTAS - 1u) {
            atomicExch(&g_bar_count, 0u);
            __threadfence();
            atomicExch(&g_bar_epoch, next);
        } else {
            while (*((volatile unsigned*)&g_bar_epoch) != next) { }
        }
        epoch = next;
    }
    __syncthreads();
}

// ---------------------------------------------------------------------------
// SMEM: WA[2048][16], WB[1024][8], RED[8*16*32], Ps[256], Rs[256],
// ACT = 3 x 16KB ring.  Total = 57856 floats = 231,424 B (< 232,448 cap).
// ---------------------------------------------------------------------------
#define SMEM_FLOATS (2048*16 + 1024*8 + 4096 + 256 + 256 + NBUF*CHUNK_FLOATS)
#define SMEM_BYTES  (SMEM_FLOATS * 4)

__global__ void __launch_bounds__(NTHR, 1)
scan_kernel(const float* __restrict__ Wxh, const float* __restrict__ Whh,
            const float* __restrict__ Wrh, const float* __restrict__ Wxr,
            const float* __restrict__ Whr, int layer)
{
    extern __shared__ float sm[];
    float* WA  = sm;                        // 2048*16
    float* WB  = WA + 2048 * 16;            // 1024*8
    float* RED = WB + 1024 * 8;             // 4096
    float* Ps  = RED + 4096;                // 256
    float* Rs  = Ps + 256;                  // 256
    float* ACT = Rs + 256;                  // NBUF * 4096

    const int tid  = threadIdx.x;
    const int cta  = blockIdx.x;
    const int c8   = cta * 8;
    const int lane = tid & 31;
    const int warp = tid >> 5;

    const size_t DR = (size_t)D_DIM * D_DIM;
    const float* wxh = Wxh + (size_t)layer * DR;
    const float* whh = Whh + (size_t)layer * DR;
    const float* wrh = Wrh + (size_t)layer * DR;
    const float* wxr = Wxr + (size_t)layer * DR;
    const float* whr = Whr + (size_t)layer * DR;

    // ---- weight slices -> SMEM (once per layer) ----
    for (int i = tid; i < 8192; i += NTHR) {
        int k  = i >> 3;
        int jc = i & 7;
        int g  = k * D_DIM + c8 + jc;
        WA[k * 16 + jc]              = wxr[g];
        WA[k * 16 + 8 + jc]          = wxh[g];
        WA[(k + 1024) * 16 + jc]     = whr[g];
        WA[(k + 1024) * 16 + 8 + jc] = whh[g];
        WB[k * 8 + jc]               = wrh[g];
    }
    // ---- zero state ----
    {
        Rs[tid] = 0.0f;
        int j = tid >> 5, b = tid & 31;
        g_hT[(c8 + j) * 32 + b] = 0.0f;
    }
    unsigned epoch = *((volatile unsigned*)&g_bar_epoch);
    __threadfence();
    grid_barrier(epoch);

    const int jj = lane >> 2;   // 0..7
    const int bb = lane & 3;    // 0..3

    // ---- t=0 phase-A prologue: first 3 x-chunks ----
    cp_chunk(ACT + 0 * CHUNK_FLOATS, g_buf,                    tid);
    cp_chunk(ACT + 1 * CHUNK_FLOATS, g_buf + CHUNK_FLOATS,     tid);
    cp_chunk(ACT + 2 * CHUNK_FLOATS, g_buf + 2 * CHUNK_FLOATS, tid);

    for (int t = 0; t < T_DIM; ++t) {
        const float* xsrc = g_buf + (size_t)t * (D_DIM * B_DIM);

        // ================= PHASE A =================
        // U[32,16] = [x_t ; h](32x2048) @ WA(2048x16); 16 chunks of 128 rows.
        {
            ull acc[8];
            #pragma unroll
            for (int i = 0; i < 8; ++i) acc[i] = 0ULL;

            #pragma unroll 1
            for (int c = 0; c < 16; ++c) {
                CP_WAIT2();               // chunk c is 3rd-most-recent group
                __syncthreads();

                const float* cb   = ACT + (c % NBUF) * CHUNK_FLOATS;
                const float* arow = cb + warp * (16 * 32) + bb * 8;
                const float* wrow = WA + (c * 128 + warp * 16) * 16;

                #pragma unroll
                for (int kl = 0; kl < 16; ++kl) {
                    ulonglong2 a01 = *(const ulonglong2*)(arow + kl * 32);
                    ulonglong2 a23 = *(const ulonglong2*)(arow + kl * 32 + 4);
                    ull wp0 = pk2(wrow[kl * 16 + jj]);
                    ull wp1 = pk2(wrow[kl * 16 + 8 + jj]);
                    ffma2(acc[0], a01.x, wp0);
                    ffma2(acc[1], a01.y, wp0);
                    ffma2(acc[2], a23.x, wp0);
                    ffma2(acc[3], a23.y, wp0);
                    ffma2(acc[4], a01.x, wp1);
                    ffma2(acc[5], a01.y, wp1);
                    ffma2(acc[6], a23.x, wp1);
                    ffma2(acc[7], a23.y, wp1);
                }
                __syncthreads();
                int nc = c + NBUF;
                if (nc < 16) {
                    const float* src = (nc < 8)
                        ? (xsrc + nc * CHUNK_FLOATS)
                        : (g_hT + (nc - 8) * CHUNK_FLOATS);
                    cp_chunk(ACT + (c % NBUF) * CHUNK_FLOATS, src, tid);
                } else {
                    CP_COMMIT_EMPTY();
                }
            }

            float* rw = RED + warp * 512;
            ull* p0 = (ull*)(rw + jj * 32 + bb * 8);
            p0[0] = acc[0]; p0[1] = acc[1]; p0[2] = acc[2]; p0[3] = acc[3];
            ull* p1 = (ull*)(rw + (jj + 8) * 32 + bb * 8);
            p1[0] = acc[4]; p1[1] = acc[5]; p1[2] = acc[6]; p1[3] = acc[7];
        }
        __syncthreads();
        // cross-warp reduce + r update / p stash
        #pragma unroll
        for (int o = tid; o < 512; o += NTHR) {
            float s = 0.0f;
            #pragma unroll
            for (int w = 0; w < 8; ++w) s += RED[w * 512 + o];
            int j = o >> 5, b = o & 31;
            if (j < 8) {
                float g  = tanhf(s);
                float rn = 0.9f * Rs[o] + 0.1f * g;
                Rs[o] = rn;
                g_rT[(c8 + j) * 32 + b] = rn;
            } else {
                Ps[o - 256] = s;
            }
        }
        __threadfence();
        grid_barrier(epoch);   // r_new globally visible

        // ================= PHASE B =================
        // Z[32,8] = r_new(32x1024) @ WB(1024x8); 8 chunks of 128 rows.
        {
            cp_chunk(ACT + 0 * CHUNK_FLOATS, g_rT,                    tid);
            cp_chunk(ACT + 1 * CHUNK_FLOATS, g_rT + CHUNK_FLOATS,     tid);
            cp_chunk(ACT + 2 * CHUNK_FLOATS, g_rT + 2 * CHUNK_FLOATS, tid);

            ull acc[4];
            #pragma unroll
            for (int i = 0; i < 4; ++i) acc[i] = 0ULL;

            #pragma unroll 1
            for (int c = 0; c < 8; ++c) {
                CP_WAIT2();
                __syncthreads();

                const float* cb   = ACT + (c % NBUF) * CHUNK_FLOATS;
                const float* arow = cb + warp * (16 * 32) + bb * 8;
                const float* wrow = WB + (c * 128 + warp * 16) * 8;

                #pragma unroll
                for (int kl = 0; kl < 16; ++kl) {
                    ulonglong2 a01 = *(const ulonglong2*)(arow + kl * 32);
                    ulonglong2 a23 = *(const ulonglong2*)(arow + kl * 32 + 4);
                    ull wp = pk2(wrow[kl * 8 + jj]);
                    ffma2(acc[0], a01.x, wp);
                    ffma2(acc[1], a01.y, wp);
                    ffma2(acc[2], a23.x, wp);
                    ffma2(acc[3], a23.y, wp);
                }
                __syncthreads();
                int nc = c + NBUF;
                if (nc < 8) {
                    cp_chunk(ACT + (c % NBUF) * CHUNK_FLOATS,
                             g_rT + nc * CHUNK_FLOATS, tid);
                } else {
                    CP_COMMIT_EMPTY();
                }
            }

            // cross-step prefetch: first 3 x-chunks of step t+1 (independent of
            // the coming barriers; fills during reduce-B + grid barrier).
            if (t + 1 < T_DIM) {
                const float* nx = g_buf + (size_t)(t + 1) * (D_DIM * B_DIM);
                cp_chunk(ACT + 0 * CHUNK_FLOATS, nx,                    tid);
                cp_chunk(ACT + 1 * CHUNK_FLOATS, nx + CHUNK_FLOATS,     tid);
                cp_chunk(ACT + 2 * CHUNK_FLOATS, nx + 2 * CHUNK_FLOATS, tid);
            } else {
                CP_COMMIT_EMPTY(); CP_COMMIT_EMPTY(); CP_COMMIT_EMPTY();
            }

            float* rw = RED + warp * 256;
            ull* p0 = (ull*)(rw + jj * 32 + bb * 8);
            p0[0] = acc[0]; p0[1] = acc[1]; p0[2] = acc[2]; p0[3] = acc[3];
        }
        __syncthreads();
        {
            float z = 0.0f;
            #pragma unroll
            for (int w = 0; w < 8; ++w) z += RED[w * 256 + tid];
            int j = tid >> 5, b = tid & 31;
            float hn = tanhf(Ps[tid] + z);
            g_hT[(c8 + j) * 32 + b] = hn;
            g_buf[(size_t)t * (D_DIM * B_DIM) + (c8 + j) * 32 + b] = hn;
        }
        __threadfence();
        grid_barrier(epoch);   // h_new visible before next step
    }
}

// ---------------------------------------------------------------------------
// Transposes: x[b][t][k]  <->  buf[t][k][b]
// ---------------------------------------------------------------------------
__global__ void transpose_in(const float* __restrict__ x)
{
    __shared__ float s[32][65];
    const int t  = blockIdx.y;
    const int k0 = blockIdx.x * 64;
    const int tid = threadIdx.x;

    #pragma unroll
    for (int p = 0; p < 8; ++p) {
        int b  = p * 4 + (tid >> 6);
        int kk = tid & 63;
        s[b][kk] = x[(size_t)b * TD_STRIDE + (size_t)t * D_DIM + k0 + kk];
    }
    __syncthreads();
    #pragma unroll
    for (int p = 0; p < 8; ++p) {
        int kk = p * 8 + (tid >> 5);
        int b  = tid & 31;
        g_buf[(size_t)t * (D_DIM * B_DIM) + (size_t)(k0 + kk) * 32 + b] = s[b][kk];
    }
}

__global__ void transpose_out(float* __restrict__ out)
{
    __shared__ float s[64][33];
    const int t  = blockIdx.y;
    const int j0 = blockIdx.x * 64;
    const int tid = threadIdx.x;

    #pragma unroll
    for (int p = 0; p < 8; ++p) {
        int jj = p * 8 + (tid >> 5);
        int b  = tid & 31;
        s[jj][b] = g_buf[(size_t)t * (D_DIM * B_DIM) + (size_t)(j0 + jj) * 32 + b];
    }
    __syncthreads();
    #pragma unroll
    for (int p = 0; p < 8; ++p) {
        int b  = p * 4 + (tid >> 6);
        int jc = tid & 63;
        out[(size_t)b * TD_STRIDE + (size_t)t * D_DIM + j0 + jc] = s[jc][b];
    }
}

// ---------------------------------------------------------------------------
extern "C" void kernel_launch(void* const* d_in, const int* in_sizes, int n_in,
                              void* d_out, int out_size)
{
    const float* x   = (const float*)d_in[0];
    const float* Wxh = (const float*)d_in[1];
    const float* Whh = (const float*)d_in[2];
    const float* Wrh = (const float*)d_in[3];
    const float* Wxr = (const float*)d_in[4];
    const float* Whr = (const float*)d_in[5];
    float* out = (float*)d_out;

    cudaFuncSetAttribute(scan_kernel,
                         cudaFuncAttributeMaxDynamicSharedMemorySize,
                         SMEM_BYTES);

    transpose_in<<<dim3(16, 1024), NTHR>>>(x);
    scan_kernel<<<GRID_CTAS, NTHR, SMEM_BYTES>>>(Wxh, Whh, Wrh, Wxr, Whr, 0);
    scan_kernel<<<GRID_CTAS, NTHR, SMEM_BYTES>>>(Wxh, Whh, Wrh, Wxr, Whr, 1);
    transpose_out<<<dim3(16, 1024), NTHR>>>(out);
}